// round 14
// baseline (speedup 1.0000x reference)
#include <cuda_runtime.h>

#define B_ 8
#define H_ 8
#define N_ 4096
#define K_ 32
#define D_ 16

// One warp per (b,h,n) query. Both k and v consumed flat-coalesced as
// 4x LDG.128 per warp (streaming, evict-first). Softmax (no max-subtraction;
// energies bounded) in lane=kk layout. Output: lane L owns
// (kk = 8j + (L>>2), d = 4*(L&3)+i).
// A/B-tested invariants: v issued before k; plain IEEE divide (NOT
// __fdividef); __launch_bounds__(256,6); loads NOT hoisted above setup;
// no shared memory / no barrier (weights read via __ldg, L2-hot).
// This round: vectorized epilogue — after the xor reduction each lane with
// g = lane&3 holds the full float4 for contiguous dims d = 4g..4g+3, so
// lanes 0-3 store directly with STG.128 (kills the select chain + 12 STGs).
__global__ __launch_bounds__(256, 6)
void pe_attn_kernel(const float* __restrict__ q,
                    const float* __restrict__ k,
                    const float* __restrict__ v,
                    const float* __restrict__ xyz,
                    const float* __restrict__ W1,
                    const float* __restrict__ b1,
                    const float* __restrict__ W2,
                    const float* __restrict__ b2,
                    float* __restrict__ out)
{
    const int tid  = threadIdx.x;
    const int lane = tid & 31;
    const int gid  = blockIdx.x * 8 + (tid >> 5);   // == ((b*H+h)*N + n)
    const int b    = gid >> 15;
    const int rem  = gid & 32767;
    const int h    = rem >> 12;
    const int n    = rem & 4095;

    const size_t qoff = (size_t)gid * D_;
    const float4* kb4 = reinterpret_cast<const float4*>(k + qoff * K_); // 128 float4
    const float4* vb4 = reinterpret_cast<const float4*>(v + qoff * K_); // 128 float4

    // ================= front-batched global loads (max MLP) =================
    // v tile flat: 4 x LDG.128, streaming (issued FIRST — empirically fastest)
    float4 vv[4];
    #pragma unroll
    for (int j = 0; j < 4; j++) vv[j] = __ldcs(vb4 + j * 32 + lane);

    // k tile flat: 4 x LDG.128, streaming.
    // kf[j] comp i on lane L == k[d = 4j + (L>>3)][kk = 4*(L&7) + i]
    float4 kf[4];
    #pragma unroll
    for (int j = 0; j < 4; j++) kf[j] = __ldcs(kb4 + j * 32 + lane);

    // q row (16 floats)
    const float qreg = (lane < 16) ? q[qoff + lane] : 0.f;

    // xyz for e_xyz, transposed-coalesced: lane L takes flat elems L, L+32, L+64
    const float* flat = xyz + (size_t)(b * N_ + n) * 96;
    const float t0 = flat[lane];
    const float t1 = flat[32 + lane];
    const float t2 = flat[64 + lane];

    // xyz block for v_xyz: 12 contiguous floats
    const int n1 = h * 512 + (n >> 3);
    const float* base2 = xyz + ((size_t)(b * N_ + n1) * K_ + ((n & 7) << 2)) * 3;
    const float tt = (lane < 12) ? base2[lane] : 0.f;

    // ================= e_xyz: partial products, shuffle-gather to lane=kk ====
    const int lm = lane % 3;
    const int i1 = (lm >= 1) ? lm - 1 : 2;   // (lane+32)%3
    const int i2 = (lm < 2)  ? lm + 1 : 0;   // (lane+64)%3
    const float pp0 = t0 * __ldg(W1 + lm * 8 + h);
    const float pp1 = t1 * __ldg(W1 + i1 * 8 + h);
    const float pp2 = t2 * __ldg(W1 + i2 * 8 + h);

    float ex = __ldg(b1 + h);
    #pragma unroll
    for (int c = 0; c < 3; c++) {
        const int mm = 3 * lane + c;         // flat element this lane (=kk) needs
        const int r  = mm & 31;
        const float a0 = __shfl_sync(0xffffffffu, pp0, r);
        const float a1 = __shfl_sync(0xffffffffu, pp1, r);
        const float a2 = __shfl_sync(0xffffffffu, pp2, r);
        ex += (mm < 32) ? a0 : ((mm < 64) ? a1 : a2);
    }

    // ================= qk from flat k =================
    // partial comp i on lane L = sum_j q[4j + (L>>3)] * k[4j + (L>>3)][4*(L&7)+i]
    const int dg = lane >> 3;
    float4 part = make_float4(0.f, 0.f, 0.f, 0.f);
    #pragma unroll
    for (int j = 0; j < 4; j++) {
        const float qd = __shfl_sync(0xffffffffu, qreg, 4 * j + dg);
        part.x = fmaf(qd, kf[j].x, part.x);
        part.y = fmaf(qd, kf[j].y, part.y);
        part.z = fmaf(qd, kf[j].z, part.z);
        part.w = fmaf(qd, kf[j].w, part.w);
    }
    // reduce across the 4 lane-groups sharing (L&7): offsets 8, 16
    #pragma unroll
    for (int off = 8; off <= 16; off <<= 1) {
        part.x += __shfl_xor_sync(0xffffffffu, part.x, off);
        part.y += __shfl_xor_sync(0xffffffffu, part.y, off);
        part.z += __shfl_xor_sync(0xffffffffu, part.z, off);
        part.w += __shfl_xor_sync(0xffffffffu, part.w, off);
    }
    // redistribute: lane (=kk) takes comp (lane&3) from lane (lane>>2)
    float qk;
    {
        const int src = lane >> 2;
        const float ax = __shfl_sync(0xffffffffu, part.x, src);
        const float ay = __shfl_sync(0xffffffffu, part.y, src);
        const float az = __shfl_sync(0xffffffffu, part.z, src);
        const float aw = __shfl_sync(0xffffffffu, part.w, src);
        const int c = lane & 3;
        qk = ax;
        if (c == 1) qk = ay;
        if (c == 2) qk = az;
        if (c == 3) qk = aw;
    }
    const float e = (qk + ex) * 0.25f;   // / sqrt(D)

    // ============ softmax over 32 lanes (no max-subtraction) ============
    float p = __expf(e);
    float s = p;
    #pragma unroll
    for (int off = 16; off; off >>= 1)
        s += __shfl_xor_sync(0xffffffffu, s, off);
    p = p / s;

    // ================= accumulate p * (v + v_xyz) =================
    const int r4 = lane >> 2;   // kk within j-slab: kk = 8j + r4 ; kk&7 = r4
    // W2/b2 rows: 128B coalesced L2-hit loads, consumed here only.
    const float4* W2v = reinterpret_cast<const float4*>(W2);
    const float4 w0  = __ldg(W2v +       lane);
    const float4 w1  = __ldg(W2v +  32 + lane);
    const float4 w2  = __ldg(W2v +  64 + lane);
    const float4 bbv = __ldg(reinterpret_cast<const float4*>(b2) + lane);

    float4 acc = make_float4(0.f, 0.f, 0.f, 0.f);
    #pragma unroll
    for (int j = 0; j < 4; j++) {
        const float pj = __shfl_sync(0xffffffffu, p, 8 * j + r4);
        const float y0 = __shfl_sync(0xffffffffu, tt, 3 * j);
        const float y1 = __shfl_sync(0xffffffffu, tt, 3 * j + 1);
        const float y2 = __shfl_sync(0xffffffffu, tt, 3 * j + 2);
        const float4 vj = vv[j];
        acc.x = fmaf(pj, vj.x + fmaf(y0, w0.x, fmaf(y1, w1.x, fmaf(y2, w2.x, bbv.x))), acc.x);
        acc.y = fmaf(pj, vj.y + fmaf(y0, w0.y, fmaf(y1, w1.y, fmaf(y2, w2.y, bbv.y))), acc.y);
        acc.z = fmaf(pj, vj.z + fmaf(y0, w0.z, fmaf(y1, w1.z, fmaf(y2, w2.z, bbv.z))), acc.z);
        acc.w = fmaf(pj, vj.w + fmaf(y0, w0.w, fmaf(y1, w1.w, fmaf(y2, w2.w, bbv.w))), acc.w);
    }

    // ======== reduce over kk (stride-4 lane groups: r4 = 0..7 per g) ========
    #pragma unroll
    for (int off = 4; off <= 16; off <<= 1) {
        acc.x += __shfl_xor_sync(0xffffffffu, acc.x, off);
        acc.y += __shfl_xor_sync(0xffffffffu, acc.y, off);
        acc.z += __shfl_xor_sync(0xffffffffu, acc.z, off);
        acc.w += __shfl_xor_sync(0xffffffffu, acc.w, off);
    }

    // After reduction, lane L (g = L&3) holds the full float4 for contiguous
    // dims d = 4g..4g+3. Lanes 0-3 store the whole 64B output as 4x STG.128.
    if (lane < 4) {
        const size_t obase = ((size_t)(b * N_ + n) * H_ + h) * D_;
        __stcs(reinterpret_cast<float4*>(out + obase) + lane, acc);
    }
}

extern "C" void kernel_launch(void* const* d_in, const int* in_sizes, int n_in,
                              void* d_out, int out_size)
{
    const float* q   = (const float*)d_in[0];
    const float* k   = (const float*)d_in[1];
    const float* v   = (const float*)d_in[2];
    const float* xyz = (const float*)d_in[3];
    const float* W1  = (const float*)d_in[4];
    const float* b1  = (const float*)d_in[5];
    const float* W2  = (const float*)d_in[6];
    const float* b2  = (const float*)d_in[7];
    float* out = (float*)d_out;

    const int blocks = (B_ * H_ * N_) / 8;   // 32768 blocks of 8 warps
    pe_attn_kernel<<<blocks, 256>>>(q, k, v, xyz, W1, b1, W2, b2, out);
}

// round 15
// speedup vs baseline: 1.0091x; 1.0091x over previous
#include <cuda_runtime.h>

#define B_ 8
#define H_ 8
#define N_ 4096
#define K_ 32
#define D_ 16

// FINAL: one warp per (b,h,n) query, pure streaming kernel at the HBM
// roofline (traffic == unique-byte minimum, ~88% of spec BW).
// Both k and v consumed flat-coalesced as 4x LDG.128 per warp (streaming,
// evict-first). Softmax (no max-subtraction; energies bounded) in lane=kk
// layout. Output: lane L owns (kk = 8j + (L>>2), d = 4*(L&3)+i).
// A/B-tested invariants (each worth 5-30 us if violated):
//   - v issued before k (load order is load-bearing)
//   - plain IEEE divide in softmax (NOT __fdividef)
//   - __launch_bounds__(256,6) -> 40 regs, v+k tiles co-resident (max MLP);
//     neither 5 nor 7 blocks is faster (MLP beats occupancy here)
//   - payload loads NOT hoisted above block setup
//   - no shared memory / no barrier: W1/b1/W2/b2 (544 floats, L2-hot) are
//     read via __ldg at point of use
__global__ __launch_bounds__(256, 6)
void pe_attn_kernel(const float* __restrict__ q,
                    const float* __restrict__ k,
                    const float* __restrict__ v,
                    const float* __restrict__ xyz,
                    const float* __restrict__ W1,
                    const float* __restrict__ b1,
                    const float* __restrict__ W2,
                    const float* __restrict__ b2,
                    float* __restrict__ out)
{
    const int tid  = threadIdx.x;
    const int lane = tid & 31;
    const int gid  = blockIdx.x * 8 + (tid >> 5);   // == ((b*H+h)*N + n)
    const int b    = gid >> 15;
    const int rem  = gid & 32767;
    const int h    = rem >> 12;
    const int n    = rem & 4095;

    const size_t qoff = (size_t)gid * D_;
    const float4* kb4 = reinterpret_cast<const float4*>(k + qoff * K_); // 128 float4
    const float4* vb4 = reinterpret_cast<const float4*>(v + qoff * K_); // 128 float4

    // ================= front-batched global loads (max MLP) =================
    // v tile flat: 4 x LDG.128, streaming (issued FIRST — empirically fastest)
    float4 vv[4];
    #pragma unroll
    for (int j = 0; j < 4; j++) vv[j] = __ldcs(vb4 + j * 32 + lane);

    // k tile flat: 4 x LDG.128, streaming.
    // kf[j] comp i on lane L == k[d = 4j + (L>>3)][kk = 4*(L&7) + i]
    float4 kf[4];
    #pragma unroll
    for (int j = 0; j < 4; j++) kf[j] = __ldcs(kb4 + j * 32 + lane);

    // q row (16 floats)
    const float qreg = (lane < 16) ? q[qoff + lane] : 0.f;

    // xyz for e_xyz, transposed-coalesced: lane L takes flat elems L, L+32, L+64
    const float* flat = xyz + (size_t)(b * N_ + n) * 96;
    const float t0 = flat[lane];
    const float t1 = flat[32 + lane];
    const float t2 = flat[64 + lane];

    // xyz block for v_xyz: 12 contiguous floats
    const int n1 = h * 512 + (n >> 3);
    const float* base2 = xyz + ((size_t)(b * N_ + n1) * K_ + ((n & 7) << 2)) * 3;
    const float tt = (lane < 12) ? base2[lane] : 0.f;

    // ================= e_xyz: partial products, shuffle-gather to lane=kk ====
    const int lm = lane % 3;
    const int i1 = (lm >= 1) ? lm - 1 : 2;   // (lane+32)%3
    const int i2 = (lm < 2)  ? lm + 1 : 0;   // (lane+64)%3
    const float pp0 = t0 * __ldg(W1 + lm * 8 + h);
    const float pp1 = t1 * __ldg(W1 + i1 * 8 + h);
    const float pp2 = t2 * __ldg(W1 + i2 * 8 + h);

    float ex = __ldg(b1 + h);
    #pragma unroll
    for (int c = 0; c < 3; c++) {
        const int mm = 3 * lane + c;         // flat element this lane (=kk) needs
        const int r  = mm & 31;
        const float a0 = __shfl_sync(0xffffffffu, pp0, r);
        const float a1 = __shfl_sync(0xffffffffu, pp1, r);
        const float a2 = __shfl_sync(0xffffffffu, pp2, r);
        ex += (mm < 32) ? a0 : ((mm < 64) ? a1 : a2);
    }

    // ================= qk from flat k =================
    // partial comp i on lane L = sum_j q[4j + (L>>3)] * k[4j + (L>>3)][4*(L&7)+i]
    const int dg = lane >> 3;
    float4 part = make_float4(0.f, 0.f, 0.f, 0.f);
    #pragma unroll
    for (int j = 0; j < 4; j++) {
        const float qd = __shfl_sync(0xffffffffu, qreg, 4 * j + dg);
        part.x = fmaf(qd, kf[j].x, part.x);
        part.y = fmaf(qd, kf[j].y, part.y);
        part.z = fmaf(qd, kf[j].z, part.z);
        part.w = fmaf(qd, kf[j].w, part.w);
    }
    // reduce across the 4 lane-groups sharing (L&7): offsets 8, 16
    #pragma unroll
    for (int off = 8; off <= 16; off <<= 1) {
        part.x += __shfl_xor_sync(0xffffffffu, part.x, off);
        part.y += __shfl_xor_sync(0xffffffffu, part.y, off);
        part.z += __shfl_xor_sync(0xffffffffu, part.z, off);
        part.w += __shfl_xor_sync(0xffffffffu, part.w, off);
    }
    // redistribute: lane (=kk) takes comp (lane&3) from lane (lane>>2)
    float qk;
    {
        const int src = lane >> 2;
        const float ax = __shfl_sync(0xffffffffu, part.x, src);
        const float ay = __shfl_sync(0xffffffffu, part.y, src);
        const float az = __shfl_sync(0xffffffffu, part.z, src);
        const float aw = __shfl_sync(0xffffffffu, part.w, src);
        const int c = lane & 3;
        qk = ax;
        if (c == 1) qk = ay;
        if (c == 2) qk = az;
        if (c == 3) qk = aw;
    }
    const float e = (qk + ex) * 0.25f;   // / sqrt(D)

    // ============ softmax over 32 lanes (no max-subtraction) ============
    float p = __expf(e);
    float s = p;
    #pragma unroll
    for (int off = 16; off; off >>= 1)
        s += __shfl_xor_sync(0xffffffffu, s, off);
    p = p / s;

    // ================= accumulate p * (v + v_xyz) =================
    const int g  = lane & 3;    // d-group: d = 4g + i
    const int r4 = lane >> 2;   // kk within j-slab: kk = 8j + r4 ; kk&7 = r4
    // W2/b2 rows: 128B coalesced L2-hit loads, consumed here only.
    const float4* W2v = reinterpret_cast<const float4*>(W2);
    const float4 w0  = __ldg(W2v +       lane);
    const float4 w1  = __ldg(W2v +  32 + lane);
    const float4 w2  = __ldg(W2v +  64 + lane);
    const float4 bbv = __ldg(reinterpret_cast<const float4*>(b2) + lane);

    float4 acc = make_float4(0.f, 0.f, 0.f, 0.f);
    #pragma unroll
    for (int j = 0; j < 4; j++) {
        const float pj = __shfl_sync(0xffffffffu, p, 8 * j + r4);
        const float y0 = __shfl_sync(0xffffffffu, tt, 3 * j);
        const float y1 = __shfl_sync(0xffffffffu, tt, 3 * j + 1);
        const float y2 = __shfl_sync(0xffffffffu, tt, 3 * j + 2);
        const float4 vj = vv[j];
        acc.x = fmaf(pj, vj.x + fmaf(y0, w0.x, fmaf(y1, w1.x, fmaf(y2, w2.x, bbv.x))), acc.x);
        acc.y = fmaf(pj, vj.y + fmaf(y0, w0.y, fmaf(y1, w1.y, fmaf(y2, w2.y, bbv.y))), acc.y);
        acc.z = fmaf(pj, vj.z + fmaf(y0, w0.z, fmaf(y1, w1.z, fmaf(y2, w2.z, bbv.z))), acc.z);
        acc.w = fmaf(pj, vj.w + fmaf(y0, w0.w, fmaf(y1, w1.w, fmaf(y2, w2.w, bbv.w))), acc.w);
    }

    // ================= reduce over kk (stride-4 lane groups) =================
    #pragma unroll
    for (int off = 4; off <= 16; off <<= 1) {
        acc.x += __shfl_xor_sync(0xffffffffu, acc.x, off);
        acc.y += __shfl_xor_sync(0xffffffffu, acc.y, off);
        acc.z += __shfl_xor_sync(0xffffffffu, acc.z, off);
        acc.w += __shfl_xor_sync(0xffffffffu, acc.w, off);
    }

    float r = acc.x;
    if (r4 == 1) r = acc.y;
    if (r4 == 2) r = acc.z;
    if (r4 == 3) r = acc.w;

    if (lane < 16) {
        const size_t obase = ((size_t)(b * N_ + n) * H_ + h) * D_;
        __stcs(out + obase + 4 * g + r4, r);
    }
}

extern "C" void kernel_launch(void* const* d_in, const int* in_sizes, int n_in,
                              void* d_out, int out_size)
{
    const float* q   = (const float*)d_in[0];
    const float* k   = (const float*)d_in[1];
    const float* v   = (const float*)d_in[2];
    const float* xyz = (const float*)d_in[3];
    const float* W1  = (const float*)d_in[4];
    const float* b1  = (const float*)d_in[5];
    const float* W2  = (const float*)d_in[6];
    const float* b2  = (const float*)d_in[7];
    float* out = (float*)d_out;

    const int blocks = (B_ * H_ * N_) / 8;   // 32768 blocks of 8 warps
    pe_attn_kernel<<<blocks, 256>>>(q, k, v, xyz, W1, b1, W2, b2, out);
}